// round 13
// baseline (speedup 1.0000x reference)
#include <cuda_runtime.h>
#include <cuda.h>
#include <cuda_fp16.h>
#include <cstdint>

// Problem shape (fixed by dataset)
#define M_TOKENS 16384
#define K_DIM    2048
#define N_DIM    2048
#define EPS      1e-7f

// GEMM tiling: 128x256 CTA tile, 8 warps of 64x64. K-chunk = 64 fp16 = 128 B.
#define BM 128
#define BN 256
#define NSTAGE 3
#define NKT 32
#define A_BYTES 16384                 // 128 rows x 128 B
#define B_BYTES 32768                 // 256 rows x 128 B
#define STAGE_B (A_BYTES + B_BYTES)   // 49152
#define SMEM_BARS (NSTAGE * STAGE_B)  // 147456
#define FULL_BAR(s)  (SMEM_BARS + (s) * 8)
#define SMEM_TOTAL (SMEM_BARS + 32)

// Scratch (device globals)
__device__ __align__(1024) __half g_qh[(size_t)M_TOKENS * K_DIM];  // fp16 activations
__device__ __align__(1024) __half g_wh[(size_t)N_DIM * K_DIM];     // fp16 weights
__device__ float g_scales[M_TOKENS];

// ---------------------------------------------------------------------------
// Kernel 0: pack int32-marshalled weights to fp16 (exact, |w| <= 127).
// ---------------------------------------------------------------------------
__global__ __launch_bounds__(256) void pack_w_kernel(const int* __restrict__ w32) {
    const int idx = blockIdx.x * blockDim.x + threadIdx.x;
    int4 v = reinterpret_cast<const int4*>(w32)[idx];
    __half2 h0 = __halves2half2(__int2half_rn(v.x), __int2half_rn(v.y));
    __half2 h1 = __halves2half2(__int2half_rn(v.z), __int2half_rn(v.w));
    uint2 hp = make_uint2(*(uint32_t*)&h0, *(uint32_t*)&h1);
    reinterpret_cast<uint2*>(g_wh)[idx] = hp;
}

// ---------------------------------------------------------------------------
// Kernel 1: per-token dynamic int8 quantization -> fp16 values (exact).
// ---------------------------------------------------------------------------
__global__ __launch_bounds__(256) void quant_kernel(const float* __restrict__ x) {
    const int token = blockIdx.x;
    const int tid = threadIdx.x;
    const int lane = tid & 31;
    const int warp = tid >> 5;

    const float4* xr = reinterpret_cast<const float4*>(x + (size_t)token * K_DIM);
    float4 v0 = xr[tid * 2 + 0];
    float4 v1 = xr[tid * 2 + 1];

    float m = fabsf(v0.x);
    m = fmaxf(m, fabsf(v0.y)); m = fmaxf(m, fabsf(v0.z)); m = fmaxf(m, fabsf(v0.w));
    m = fmaxf(m, fabsf(v1.x)); m = fmaxf(m, fabsf(v1.y));
    m = fmaxf(m, fabsf(v1.z)); m = fmaxf(m, fabsf(v1.w));

    #pragma unroll
    for (int off = 16; off > 0; off >>= 1)
        m = fmaxf(m, __shfl_xor_sync(0xFFFFFFFFu, m, off));

    __shared__ float wmax[8];
    if (lane == 0) wmax[warp] = m;
    __syncthreads();
    if (warp == 0) {
        float t = (lane < 8) ? wmax[lane] : 0.0f;
        #pragma unroll
        for (int off = 4; off > 0; off >>= 1)
            t = fmaxf(t, __shfl_xor_sync(0xFFFFFFFFu, t, off));
        if (lane == 0) wmax[0] = t;
    }
    __syncthreads();
    const float absmax = wmax[0];
    const float scale = fmaxf(absmax, EPS) / 127.0f;

    if (tid == 0) g_scales[token] = scale;

    const float inv = 1.0f / scale;
    float vals[8] = {v0.x, v0.y, v0.z, v0.w, v1.x, v1.y, v1.z, v1.w};
    int qv[8];
    #pragma unroll
    for (int i = 0; i < 8; i++) {
        float q = rintf(vals[i] * inv);
        q = fminf(fmaxf(q, -128.0f), 127.0f);
        qv[i] = (int)q;
    }
    uint4 hq;
    __half2 h;
    h = __halves2half2(__int2half_rn(qv[0]), __int2half_rn(qv[1])); hq.x = *(uint32_t*)&h;
    h = __halves2half2(__int2half_rn(qv[2]), __int2half_rn(qv[3])); hq.y = *(uint32_t*)&h;
    h = __halves2half2(__int2half_rn(qv[4]), __int2half_rn(qv[5])); hq.z = *(uint32_t*)&h;
    h = __halves2half2(__int2half_rn(qv[6]), __int2half_rn(qv[7])); hq.w = *(uint32_t*)&h;
    *reinterpret_cast<uint4*>(g_qh + (size_t)token * K_DIM + tid * 8) = hq;
}

// ---------------------------------------------------------------------------
// PTX helpers (TMA + mbarrier)
// ---------------------------------------------------------------------------
__device__ __forceinline__ void mbar_init(uint32_t a, uint32_t cnt) {
    asm volatile("mbarrier.init.shared.b64 [%0], %1;" :: "r"(a), "r"(cnt) : "memory");
}
__device__ __forceinline__ void mbar_expect_tx(uint32_t a, uint32_t bytes) {
    asm volatile("mbarrier.arrive.expect_tx.shared.b64 _, [%0], %1;" :: "r"(a), "r"(bytes) : "memory");
}
__device__ __forceinline__ void mbar_wait(uint32_t a, uint32_t parity) {
    asm volatile(
        "{\n\t.reg .pred P;\n"
        "W1_%=:\n\t"
        "mbarrier.try_wait.parity.acquire.cta.shared::cta.b64 P, [%0], %1, 0x989680;\n\t"
        "@P bra.uni W2_%=;\n\t"
        "bra.uni W1_%=;\n"
        "W2_%=:\n\t}"
        :: "r"(a), "r"(parity) : "memory");
}
__device__ __forceinline__ void tma3d(uint32_t smem, const CUtensorMap* map, int x, int y, uint32_t mbar) {
    asm volatile(
        "cp.async.bulk.tensor.3d.shared::cta.global.tile.mbarrier::complete_tx::bytes "
        "[%0], [%1, {%2, %3, %4}], [%5];"
        :: "r"(smem), "l"(map), "r"(x), "r"(y), "r"(0), "r"(mbar) : "memory");
}
__device__ __forceinline__ void ldsm4(uint32_t& r0, uint32_t& r1, uint32_t& r2, uint32_t& r3,
                                      uint32_t addr) {
    asm volatile("ldmatrix.sync.aligned.m8n8.x4.shared.b16 {%0,%1,%2,%3}, [%4];"
                 : "=r"(r0), "=r"(r1), "=r"(r2), "=r"(r3) : "r"(addr));
}

// ---------------------------------------------------------------------------
// Kernel 2: fp16 HMMA GEMM, 128x256 CTA tile (8 warps x 64x64), TMA +
// FULL-mbarrier + syncthreads-fenced recycle (race-free). 1 CTA/SM.
// Launched twice (half-M each) for ncu visibility.
// ---------------------------------------------------------------------------
__global__ __launch_bounds__(256, 1) void gemm_f16_kernel(
    const __grid_constant__ CUtensorMap tma_a,
    const __grid_constant__ CUtensorMap tma_b,
    const float* __restrict__ w_scale,
    const float* __restrict__ bias,
    float* __restrict__ out,
    int m_base)
{
    extern __shared__ char smem[];
    const uint32_t sb = (uint32_t)__cvta_generic_to_shared(smem);

    const int tid = threadIdx.x;
    const int lane = tid & 31;
    const int warp = tid >> 5;
    const int warpM = warp >> 2;   // 0..1 (64 rows)
    const int warpN = warp & 3;    // 0..3 (64 cols)
    const int g = lane >> 2;
    const int tg = lane & 3;

    const int m0 = m_base + blockIdx.y * BM;
    const int n0 = blockIdx.x * BN;

    if (tid == 0) {
        #pragma unroll
        for (int s = 0; s < NSTAGE; s++) mbar_init(sb + FULL_BAR(s), 1);
    }
    __syncthreads();

    // Prologue: fill all NSTAGE stages with chunks 0..NSTAGE-1.
    if (tid == 0) {
        #pragma unroll
        for (int s = 0; s < NSTAGE; s++) {
            mbar_expect_tx(sb + FULL_BAR(s), STAGE_B);
            tma3d(sb + s * STAGE_B,           &tma_a, s * 128, m0, sb + FULL_BAR(s));
            tma3d(sb + s * STAGE_B + A_BYTES, &tma_b, s * 128, n0, sb + FULL_BAR(s));
        }
    }

    float acc[4][8][4];
    #pragma unroll
    for (int mi = 0; mi < 4; mi++)
        #pragma unroll
        for (int ni = 0; ni < 8; ni++)
            #pragma unroll
            for (int r = 0; r < 4; r++) acc[mi][ni][r] = 0.0f;

    // ldmatrix lane rows (validated layout) + SW128 per-lane XOR masks.
    const int aRow = warpM * 64 + (lane & 7) + ((lane >> 3) & 1) * 8;   // + mi*16
    const int aKof = (lane >> 4) * 16;
    const int bRow = warpN * 64 + (lane >> 4) * 8 + (lane & 7);         // + j2*16
    const int bKof = ((lane >> 3) & 1) * 16;
    const int aXor = (aRow & 7) * 16;
    const int bXor = (bRow & 7) * 16;

    int cstage = 0, cph = 0;

    for (int kt = 0; kt < NKT; kt++) {
        mbar_wait(sb + FULL_BAR(cstage), cph);
        const uint32_t aBase = sb + cstage * STAGE_B;
        const uint32_t bBase = aBase + A_BYTES;

        #pragma unroll
        for (int ks = 0; ks < 4; ks++) {
            const int k0 = ks * 32;
            uint32_t afr[4][4];
            #pragma unroll
            for (int mi = 0; mi < 4; mi++) {
                const int row = aRow + mi * 16;
                ldsm4(afr[mi][0], afr[mi][1], afr[mi][2], afr[mi][3],
                      aBase + row * 128 + ((k0 + aKof) ^ aXor));
            }
            uint32_t bfr[8][2];
            #pragma unroll
            for (int j2 = 0; j2 < 4; j2++) {
                const int row = bRow + j2 * 16;
                uint32_t b0, b1, b2, b3;
                ldsm4(b0, b1, b2, b3, bBase + row * 128 + ((k0 + bKof) ^ bXor));
                bfr[2 * j2][0] = b0; bfr[2 * j2][1] = b1;
                bfr[2 * j2 + 1][0] = b2; bfr[2 * j2 + 1][1] = b3;
            }
            #pragma unroll
            for (int mi = 0; mi < 4; mi++)
                #pragma unroll
                for (int ni = 0; ni < 8; ni++) {
                    asm volatile(
                        "mma.sync.aligned.m16n8k16.row.col.f32.f16.f16.f32 "
                        "{%0,%1,%2,%3}, {%4,%5,%6,%7}, {%8,%9}, {%0,%1,%2,%3};\n"
                        : "+f"(acc[mi][ni][0]), "+f"(acc[mi][ni][1]),
                          "+f"(acc[mi][ni][2]), "+f"(acc[mi][ni][3])
                        : "r"(afr[mi][0]), "r"(afr[mi][1]), "r"(afr[mi][2]), "r"(afr[mi][3]),
                          "r"(bfr[ni][0]), "r"(bfr[ni][1]));
                }
        }

        // Full fence: every thread has finished reading stage cstage.
        __syncthreads();

        // Refill the just-freed stage with chunk kt+NSTAGE.
        const int pf = kt + NSTAGE;
        if (tid == 0 && pf < NKT) {
            mbar_expect_tx(sb + FULL_BAR(cstage), STAGE_B);
            tma3d(sb + cstage * STAGE_B,           &tma_a, pf * 128, m0, sb + FULL_BAR(cstage));
            tma3d(sb + cstage * STAGE_B + A_BYTES, &tma_b, pf * 128, n0, sb + FULL_BAR(cstage));
        }

        if (++cstage == NSTAGE) { cstage = 0; cph ^= 1; }
    }

    // Epilogue: dequant + bias, round through fp16, store fp32 (validated).
    #pragma unroll
    for (int mi = 0; mi < 4; mi++) {
        const int r0 = m0 + warpM * 64 + mi * 16 + g;
        const float s0 = g_scales[r0];
        const float s1 = g_scales[r0 + 8];
        #pragma unroll
        for (int ni = 0; ni < 8; ni++) {
            const int c = n0 + warpN * 64 + ni * 8 + tg * 2;
            const float w0 = w_scale[c], w1 = w_scale[c + 1];
            const float b0 = bias[c],    b1 = bias[c + 1];
            float2 o0, o1;
            o0.x = __half2float(__float2half_rn(acc[mi][ni][0] * s0 * w0 + b0));
            o0.y = __half2float(__float2half_rn(acc[mi][ni][1] * s0 * w1 + b1));
            o1.x = __half2float(__float2half_rn(acc[mi][ni][2] * s1 * w0 + b0));
            o1.y = __half2float(__float2half_rn(acc[mi][ni][3] * s1 * w1 + b1));
            *reinterpret_cast<float2*>(out + (size_t)r0 * N_DIM + c) = o0;
            *reinterpret_cast<float2*>(out + (size_t)(r0 + 8) * N_DIM + c) = o1;
        }
    }
}

// ---------------------------------------------------------------------------
// Host launcher
// ---------------------------------------------------------------------------
typedef CUresult (*PFN_encodeTiled)(
    CUtensorMap*, CUtensorMapDataType, cuuint32_t, void*,
    const cuuint64_t*, const cuuint64_t*, const cuuint32_t*, const cuuint32_t*,
    CUtensorMapInterleave, CUtensorMapSwizzle, CUtensorMapL2promotion,
    CUtensorMapFloatOOBfill);

extern "C" void kernel_launch(void* const* d_in, const int* in_sizes, int n_in,
                              void* d_out, int out_size) {
    const float* x       = (const float*)d_in[0];
    const int*   weight  = (const int*)d_in[1];   // int8 marshalled as int32
    const float* w_scale = (const float*)d_in[2];
    const float* bias    = (const float*)d_in[3];
    float* out = (float*)d_out;

    pack_w_kernel<<<(N_DIM * K_DIM / 4) / 256, 256>>>(weight);
    quant_kernel<<<M_TOKENS, 256>>>(x);

    void* qptr = nullptr;
    void* wptr = nullptr;
    cudaGetSymbolAddress(&qptr, g_qh);
    cudaGetSymbolAddress(&wptr, g_wh);

    PFN_encodeTiled enc = nullptr;
    cudaDriverEntryPointQueryResult qres;
    cudaGetDriverEntryPointByVersion("cuTensorMapEncodeTiled", (void**)&enc, 12000,
                                     cudaEnableDefault, &qres);

    // Byte-typed views of the fp16 matrices: dims {K bytes, rows, 1}, SW128.
    CUtensorMap ta, tb;
    cuuint64_t dimsA[3] = {K_DIM * 2, M_TOKENS, 1};
    cuuint64_t strA[2]  = {K_DIM * 2, (cuuint64_t)(K_DIM * 2) * M_TOKENS};
    cuuint64_t dimsB[3] = {K_DIM * 2, N_DIM, 1};
    cuuint64_t strB[2]  = {K_DIM * 2, (cuuint64_t)(K_DIM * 2) * N_DIM};
    cuuint32_t boxA[3]  = {128, 128, 1};
    cuuint32_t boxB[3]  = {128, 256, 1};
    cuuint32_t es[3]    = {1, 1, 1};

    enc(&ta, CU_TENSOR_MAP_DATA_TYPE_UINT8, 3, qptr, dimsA, strA, boxA, es,
        CU_TENSOR_MAP_INTERLEAVE_NONE, CU_TENSOR_MAP_SWIZZLE_128B,
        CU_TENSOR_MAP_L2_PROMOTION_L2_128B, CU_TENSOR_MAP_FLOAT_OOB_FILL_NONE);
    enc(&tb, CU_TENSOR_MAP_DATA_TYPE_UINT8, 3, wptr, dimsB, strB, boxB, es,
        CU_TENSOR_MAP_INTERLEAVE_NONE, CU_TENSOR_MAP_SWIZZLE_128B,
        CU_TENSOR_MAP_L2_PROMOTION_L2_128B, CU_TENSOR_MAP_FLOAT_OOB_FILL_NONE);

    cudaFuncSetAttribute(gemm_f16_kernel, cudaFuncAttributeMaxDynamicSharedMemorySize, SMEM_TOTAL);
    dim3 grid(N_DIM / BN, M_TOKENS / BM / 2);   // (8, 64) per half
    gemm_f16_kernel<<<grid, 256, SMEM_TOTAL>>>(ta, tb, w_scale, bias, out, 0);
    gemm_f16_kernel<<<grid, 256, SMEM_TOTAL>>>(ta, tb, w_scale, bias, out, M_TOKENS / 2);
}

// round 14
// speedup vs baseline: 1.7288x; 1.7288x over previous
#include <cuda_runtime.h>
#include <cuda.h>
#include <cuda_fp16.h>
#include <cstdint>

// Problem shape (fixed by dataset)
#define M_TOKENS 16384
#define K_DIM    2048
#define N_DIM    2048
#define EPS      1e-7f

// GEMM tiling: 128x128 CTA tile, K-chunk = 64 fp16 = 128 B per stage
#define BM 128
#define BN 128
#define NSTAGE 3
#define NKT 32
#define STAGE_B 32768                 // A 16KB + B 16KB, SW128-swizzled, pitch 128
#define SMEM_BARS (NSTAGE * STAGE_B)  // 98304
#define FULL_BAR(s)  (SMEM_BARS + (s) * 8)
#define SMEM_TOTAL (SMEM_BARS + 32)

// Scratch (device globals)
__device__ __align__(1024) __half g_qh[(size_t)M_TOKENS * K_DIM];  // fp16 activations
__device__ __align__(1024) __half g_wh[(size_t)N_DIM * K_DIM];     // fp16 weights
__device__ float g_scales[M_TOKENS];

// ---------------------------------------------------------------------------
// Kernel 0: pack int32-marshalled weights to fp16 (exact, |w| <= 127).
// ---------------------------------------------------------------------------
__global__ __launch_bounds__(256) void pack_w_kernel(const int* __restrict__ w32) {
    const int idx = blockIdx.x * blockDim.x + threadIdx.x;
    int4 v = reinterpret_cast<const int4*>(w32)[idx];
    __half2 h0 = __halves2half2(__int2half_rn(v.x), __int2half_rn(v.y));
    __half2 h1 = __halves2half2(__int2half_rn(v.z), __int2half_rn(v.w));
    uint2 hp = make_uint2(*(uint32_t*)&h0, *(uint32_t*)&h1);
    reinterpret_cast<uint2*>(g_wh)[idx] = hp;
}

// ---------------------------------------------------------------------------
// Kernel 1: per-token dynamic int8 quantization -> fp16 values (exact).
// ---------------------------------------------------------------------------
__global__ __launch_bounds__(256) void quant_kernel(const float* __restrict__ x) {
    const int token = blockIdx.x;
    const int tid = threadIdx.x;
    const int lane = tid & 31;
    const int warp = tid >> 5;

    const float4* xr = reinterpret_cast<const float4*>(x + (size_t)token * K_DIM);
    float4 v0 = xr[tid * 2 + 0];
    float4 v1 = xr[tid * 2 + 1];

    float m = fabsf(v0.x);
    m = fmaxf(m, fabsf(v0.y)); m = fmaxf(m, fabsf(v0.z)); m = fmaxf(m, fabsf(v0.w));
    m = fmaxf(m, fabsf(v1.x)); m = fmaxf(m, fabsf(v1.y));
    m = fmaxf(m, fabsf(v1.z)); m = fmaxf(m, fabsf(v1.w));

    #pragma unroll
    for (int off = 16; off > 0; off >>= 1)
        m = fmaxf(m, __shfl_xor_sync(0xFFFFFFFFu, m, off));

    __shared__ float wmax[8];
    if (lane == 0) wmax[warp] = m;
    __syncthreads();
    if (warp == 0) {
        float t = (lane < 8) ? wmax[lane] : 0.0f;
        #pragma unroll
        for (int off = 4; off > 0; off >>= 1)
            t = fmaxf(t, __shfl_xor_sync(0xFFFFFFFFu, t, off));
        if (lane == 0) wmax[0] = t;
    }
    __syncthreads();
    const float absmax = wmax[0];
    const float scale = fmaxf(absmax, EPS) / 127.0f;

    if (tid == 0) g_scales[token] = scale;

    const float inv = 1.0f / scale;
    float vals[8] = {v0.x, v0.y, v0.z, v0.w, v1.x, v1.y, v1.z, v1.w};
    int qv[8];
    #pragma unroll
    for (int i = 0; i < 8; i++) {
        float q = rintf(vals[i] * inv);
        q = fminf(fmaxf(q, -128.0f), 127.0f);
        qv[i] = (int)q;
    }
    uint4 hq;
    __half2 h;
    h = __halves2half2(__int2half_rn(qv[0]), __int2half_rn(qv[1])); hq.x = *(uint32_t*)&h;
    h = __halves2half2(__int2half_rn(qv[2]), __int2half_rn(qv[3])); hq.y = *(uint32_t*)&h;
    h = __halves2half2(__int2half_rn(qv[4]), __int2half_rn(qv[5])); hq.z = *(uint32_t*)&h;
    h = __halves2half2(__int2half_rn(qv[6]), __int2half_rn(qv[7])); hq.w = *(uint32_t*)&h;
    *reinterpret_cast<uint4*>(g_qh + (size_t)token * K_DIM + tid * 8) = hq;
}

// ---------------------------------------------------------------------------
// PTX helpers (TMA + mbarrier)
// ---------------------------------------------------------------------------
__device__ __forceinline__ void mbar_init(uint32_t a, uint32_t cnt) {
    asm volatile("mbarrier.init.shared.b64 [%0], %1;" :: "r"(a), "r"(cnt) : "memory");
}
__device__ __forceinline__ void mbar_expect_tx(uint32_t a, uint32_t bytes) {
    asm volatile("mbarrier.arrive.expect_tx.shared.b64 _, [%0], %1;" :: "r"(a), "r"(bytes) : "memory");
}
__device__ __forceinline__ void mbar_wait(uint32_t a, uint32_t parity) {
    asm volatile(
        "{\n\t.reg .pred P;\n"
        "W1_%=:\n\t"
        "mbarrier.try_wait.parity.acquire.cta.shared::cta.b64 P, [%0], %1, 0x989680;\n\t"
        "@P bra.uni W2_%=;\n\t"
        "bra.uni W1_%=;\n"
        "W2_%=:\n\t}"
        :: "r"(a), "r"(parity) : "memory");
}
__device__ __forceinline__ void tma3d(uint32_t smem, const CUtensorMap* map, int x, int y, uint32_t mbar) {
    asm volatile(
        "cp.async.bulk.tensor.3d.shared::cta.global.tile.mbarrier::complete_tx::bytes "
        "[%0], [%1, {%2, %3, %4}], [%5];"
        :: "r"(smem), "l"(map), "r"(x), "r"(y), "r"(0), "r"(mbar) : "memory");
}
__device__ __forceinline__ void ldsm4(uint32_t& r0, uint32_t& r1, uint32_t& r2, uint32_t& r3,
                                      uint32_t addr) {
    asm volatile("ldmatrix.sync.aligned.m8n8.x4.shared.b16 {%0,%1,%2,%3}, [%4];"
                 : "=r"(r0), "=r"(r1), "=r"(r2), "=r"(r3) : "r"(addr));
}

// ---------------------------------------------------------------------------
// Kernel 2: fp16 HMMA GEMM, TMA + FULL-mbarrier pipeline with syncthreads-
// fenced stage recycling (race-free, validated R11). SW128 smem, 128x128
// tile, 2 CTAs/SM. ONE launch: 2048 CTAs -> 6.92 waves (no tail doubling).
// ---------------------------------------------------------------------------
__global__ __launch_bounds__(256, 2) void gemm_f16_kernel(
    const __grid_constant__ CUtensorMap tma_a,
    const __grid_constant__ CUtensorMap tma_b,
    const float* __restrict__ w_scale,
    const float* __restrict__ bias,
    float* __restrict__ out)
{
    extern __shared__ char smem[];
    const uint32_t sb = (uint32_t)__cvta_generic_to_shared(smem);

    const int tid = threadIdx.x;
    const int lane = tid & 31;
    const int warp = tid >> 5;
    const int warpM = warp >> 2;   // 0..1 (64 rows)
    const int warpN = warp & 3;    // 0..3 (32 cols)
    const int g = lane >> 2;
    const int tg = lane & 3;

    const int m0 = blockIdx.y * BM;
    const int n0 = blockIdx.x * BN;

    if (tid == 0) {
        #pragma unroll
        for (int s = 0; s < NSTAGE; s++) mbar_init(sb + FULL_BAR(s), 1);
    }
    __syncthreads();

    // Prologue: fill all NSTAGE stages with chunks 0..NSTAGE-1.
    if (tid == 0) {
        #pragma unroll
        for (int s = 0; s < NSTAGE; s++) {
            mbar_expect_tx(sb + FULL_BAR(s), STAGE_B);
            tma3d(sb + s * STAGE_B,         &tma_a, s * 128, m0, sb + FULL_BAR(s));
            tma3d(sb + s * STAGE_B + 16384, &tma_b, s * 128, n0, sb + FULL_BAR(s));
        }
    }

    float acc[4][4][4];
    #pragma unroll
    for (int mi = 0; mi < 4; mi++)
        #pragma unroll
        for (int ni = 0; ni < 4; ni++)
            #pragma unroll
            for (int r = 0; r < 4; r++) acc[mi][ni][r] = 0.0f;

    // ldmatrix lane rows (validated layout) + SW128 per-lane XOR masks.
    const int aRow = warpM * 64 + (lane & 7) + ((lane >> 3) & 1) * 8;   // + mi*16
    const int aKof = (lane >> 4) * 16;
    const int bRow = warpN * 32 + (lane >> 4) * 8 + (lane & 7);         // + j2*16
    const int bKof = ((lane >> 3) & 1) * 16;
    const int aXor = (aRow & 7) * 16;
    const int bXor = (bRow & 7) * 16;

    int cstage = 0, cph = 0;

    for (int kt = 0; kt < NKT; kt++) {
        // Wait for this stage's TMA data.
        mbar_wait(sb + FULL_BAR(cstage), cph);
        const uint32_t aBase = sb + cstage * STAGE_B;
        const uint32_t bBase = aBase + 16384;

        #pragma unroll
        for (int ks = 0; ks < 4; ks++) {
            const int k0 = ks * 32;
            uint32_t afr[4][4];
            #pragma unroll
            for (int mi = 0; mi < 4; mi++) {
                const int row = aRow + mi * 16;
                ldsm4(afr[mi][0], afr[mi][1], afr[mi][2], afr[mi][3],
                      aBase + row * 128 + ((k0 + aKof) ^ aXor));
            }
            uint32_t bfr[4][2];
            #pragma unroll
            for (int j2 = 0; j2 < 2; j2++) {
                const int row = bRow + j2 * 16;
                uint32_t b0, b1, b2, b3;
                ldsm4(b0, b1, b2, b3, bBase + row * 128 + ((k0 + bKof) ^ bXor));
                bfr[2 * j2][0] = b0; bfr[2 * j2][1] = b1;
                bfr[2 * j2 + 1][0] = b2; bfr[2 * j2 + 1][1] = b3;
            }
            #pragma unroll
            for (int mi = 0; mi < 4; mi++)
                #pragma unroll
                for (int ni = 0; ni < 4; ni++) {
                    asm volatile(
                        "mma.sync.aligned.m16n8k16.row.col.f32.f16.f16.f32 "
                        "{%0,%1,%2,%3}, {%4,%5,%6,%7}, {%8,%9}, {%0,%1,%2,%3};\n"
                        : "+f"(acc[mi][ni][0]), "+f"(acc[mi][ni][1]),
                          "+f"(acc[mi][ni][2]), "+f"(acc[mi][ni][3])
                        : "r"(afr[mi][0]), "r"(afr[mi][1]), "r"(afr[mi][2]), "r"(afr[mi][3]),
                          "r"(bfr[ni][0]), "r"(bfr[ni][1]));
                }
        }

        // Full fence: every thread has finished reading stage cstage.
        __syncthreads();

        // Refill the just-freed stage with chunk kt+NSTAGE.
        const int pf = kt + NSTAGE;
        if (tid == 0 && pf < NKT) {
            mbar_expect_tx(sb + FULL_BAR(cstage), STAGE_B);
            tma3d(sb + cstage * STAGE_B,         &tma_a, pf * 128, m0, sb + FULL_BAR(cstage));
            tma3d(sb + cstage * STAGE_B + 16384, &tma_b, pf * 128, n0, sb + FULL_BAR(cstage));
        }

        if (++cstage == NSTAGE) { cstage = 0; cph ^= 1; }
    }

    // Epilogue: dequant + bias, round through fp16, store fp32 (validated).
    #pragma unroll
    for (int mi = 0; mi < 4; mi++) {
        const int r0 = m0 + warpM * 64 + mi * 16 + g;
        const float s0 = g_scales[r0];
        const float s1 = g_scales[r0 + 8];
        #pragma unroll
        for (int ni = 0; ni < 4; ni++) {
            const int c = n0 + warpN * 32 + ni * 8 + tg * 2;
            const float w0 = w_scale[c], w1 = w_scale[c + 1];
            const float b0 = bias[c],    b1 = bias[c + 1];
            float2 o0, o1;
            o0.x = __half2float(__float2half_rn(acc[mi][ni][0] * s0 * w0 + b0));
            o0.y = __half2float(__float2half_rn(acc[mi][ni][1] * s0 * w1 + b1));
            o1.x = __half2float(__float2half_rn(acc[mi][ni][2] * s1 * w0 + b0));
            o1.y = __half2float(__float2half_rn(acc[mi][ni][3] * s1 * w1 + b1));
            *reinterpret_cast<float2*>(out + (size_t)r0 * N_DIM + c) = o0;
            *reinterpret_cast<float2*>(out + (size_t)(r0 + 8) * N_DIM + c) = o1;
        }
    }
}

// ---------------------------------------------------------------------------
// Host launcher
// ---------------------------------------------------------------------------
typedef CUresult (*PFN_encodeTiled)(
    CUtensorMap*, CUtensorMapDataType, cuuint32_t, void*,
    const cuuint64_t*, const cuuint64_t*, const cuuint32_t*, const cuuint32_t*,
    CUtensorMapInterleave, CUtensorMapSwizzle, CUtensorMapL2promotion,
    CUtensorMapFloatOOBfill);

extern "C" void kernel_launch(void* const* d_in, const int* in_sizes, int n_in,
                              void* d_out, int out_size) {
    const float* x       = (const float*)d_in[0];
    const int*   weight  = (const int*)d_in[1];   // int8 marshalled as int32
    const float* w_scale = (const float*)d_in[2];
    const float* bias    = (const float*)d_in[3];
    float* out = (float*)d_out;

    pack_w_kernel<<<(N_DIM * K_DIM / 4) / 256, 256>>>(weight);
    quant_kernel<<<M_TOKENS, 256>>>(x);

    void* qptr = nullptr;
    void* wptr = nullptr;
    cudaGetSymbolAddress(&qptr, g_qh);
    cudaGetSymbolAddress(&wptr, g_wh);

    PFN_encodeTiled enc = nullptr;
    cudaDriverEntryPointQueryResult qres;
    cudaGetDriverEntryPointByVersion("cuTensorMapEncodeTiled", (void**)&enc, 12000,
                                     cudaEnableDefault, &qres);

    // Byte-typed views of the fp16 matrices: dims {K bytes, rows, 1}, SW128.
    CUtensorMap ta, tb;
    cuuint64_t dimsA[3] = {K_DIM * 2, M_TOKENS, 1};
    cuuint64_t strA[2]  = {K_DIM * 2, (cuuint64_t)(K_DIM * 2) * M_TOKENS};
    cuuint64_t dimsB[3] = {K_DIM * 2, N_DIM, 1};
    cuuint64_t strB[2]  = {K_DIM * 2, (cuuint64_t)(K_DIM * 2) * N_DIM};
    cuuint32_t box[3]   = {128, 128, 1};
    cuuint32_t es[3]    = {1, 1, 1};

    enc(&ta, CU_TENSOR_MAP_DATA_TYPE_UINT8, 3, qptr, dimsA, strA, box, es,
        CU_TENSOR_MAP_INTERLEAVE_NONE, CU_TENSOR_MAP_SWIZZLE_128B,
        CU_TENSOR_MAP_L2_PROMOTION_L2_128B, CU_TENSOR_MAP_FLOAT_OOB_FILL_NONE);
    enc(&tb, CU_TENSOR_MAP_DATA_TYPE_UINT8, 3, wptr, dimsB, strB, box, es,
        CU_TENSOR_MAP_INTERLEAVE_NONE, CU_TENSOR_MAP_SWIZZLE_128B,
        CU_TENSOR_MAP_L2_PROMOTION_L2_128B, CU_TENSOR_MAP_FLOAT_OOB_FILL_NONE);

    cudaFuncSetAttribute(gemm_f16_kernel, cudaFuncAttributeMaxDynamicSharedMemorySize, SMEM_TOTAL);
    dim3 grid(N_DIM / BN, M_TOKENS / BM);   // (16, 128) = 2048 CTAs, one launch
    gemm_f16_kernel<<<grid, 256, SMEM_TOTAL>>>(ta, tb, w_scale, bias, out);
}

// round 15
// speedup vs baseline: 1.8063x; 1.0448x over previous
#include <cuda_runtime.h>
#include <cuda.h>
#include <cuda_fp16.h>
#include <cstdint>

// Problem shape (fixed by dataset)
#define M_TOKENS 16384
#define K_DIM    2048
#define N_DIM    2048
#define EPS      1e-7f

// GEMM tiling: 128x128 CTA tile, K-chunk = 64 fp16 = 128 B per stage
#define BM 128
#define BN 128
#define NSTAGE 3
#define NKT 32
#define STAGE_B 32768                 // A 16KB + B 16KB, SW128-swizzled, pitch 128
#define SMEM_BARS (NSTAGE * STAGE_B)  // 98304
#define FULL_BAR(s)  (SMEM_BARS + (s) * 8)
#define EMPTY_BAR(s) (SMEM_BARS + 32 + (s) * 8)
#define SMEM_TOTAL (SMEM_BARS + 64)

// Scratch (device globals)
__device__ __align__(1024) __half g_qh[(size_t)M_TOKENS * K_DIM];  // fp16 activations
__device__ __align__(1024) __half g_wh[(size_t)N_DIM * K_DIM];     // fp16 weights
__device__ float g_scales[M_TOKENS];

// ---------------------------------------------------------------------------
// Kernel 0: pack int32-marshalled weights to fp16 (exact, |w| <= 127).
// ---------------------------------------------------------------------------
__global__ __launch_bounds__(256) void pack_w_kernel(const int* __restrict__ w32) {
    const int idx = blockIdx.x * blockDim.x + threadIdx.x;
    int4 v = reinterpret_cast<const int4*>(w32)[idx];
    __half2 h0 = __halves2half2(__int2half_rn(v.x), __int2half_rn(v.y));
    __half2 h1 = __halves2half2(__int2half_rn(v.z), __int2half_rn(v.w));
    uint2 hp = make_uint2(*(uint32_t*)&h0, *(uint32_t*)&h1);
    reinterpret_cast<uint2*>(g_wh)[idx] = hp;
}

// ---------------------------------------------------------------------------
// Kernel 1: per-token dynamic int8 quantization -> fp16 values (exact).
// ---------------------------------------------------------------------------
__global__ __launch_bounds__(256) void quant_kernel(const float* __restrict__ x) {
    const int token = blockIdx.x;
    const int tid = threadIdx.x;
    const int lane = tid & 31;
    const int warp = tid >> 5;

    const float4* xr = reinterpret_cast<const float4*>(x + (size_t)token * K_DIM);
    float4 v0 = xr[tid * 2 + 0];
    float4 v1 = xr[tid * 2 + 1];

    float m = fabsf(v0.x);
    m = fmaxf(m, fabsf(v0.y)); m = fmaxf(m, fabsf(v0.z)); m = fmaxf(m, fabsf(v0.w));
    m = fmaxf(m, fabsf(v1.x)); m = fmaxf(m, fabsf(v1.y));
    m = fmaxf(m, fabsf(v1.z)); m = fmaxf(m, fabsf(v1.w));

    #pragma unroll
    for (int off = 16; off > 0; off >>= 1)
        m = fmaxf(m, __shfl_xor_sync(0xFFFFFFFFu, m, off));

    __shared__ float wmax[8];
    if (lane == 0) wmax[warp] = m;
    __syncthreads();
    if (warp == 0) {
        float t = (lane < 8) ? wmax[lane] : 0.0f;
        #pragma unroll
        for (int off = 4; off > 0; off >>= 1)
            t = fmaxf(t, __shfl_xor_sync(0xFFFFFFFFu, t, off));
        if (lane == 0) wmax[0] = t;
    }
    __syncthreads();
    const float absmax = wmax[0];
    const float scale = fmaxf(absmax, EPS) / 127.0f;

    if (tid == 0) g_scales[token] = scale;

    const float inv = 1.0f / scale;
    float vals[8] = {v0.x, v0.y, v0.z, v0.w, v1.x, v1.y, v1.z, v1.w};
    int qv[8];
    #pragma unroll
    for (int i = 0; i < 8; i++) {
        float q = rintf(vals[i] * inv);
        q = fminf(fmaxf(q, -128.0f), 127.0f);
        qv[i] = (int)q;
    }
    uint4 hq;
    __half2 h;
    h = __halves2half2(__int2half_rn(qv[0]), __int2half_rn(qv[1])); hq.x = *(uint32_t*)&h;
    h = __halves2half2(__int2half_rn(qv[2]), __int2half_rn(qv[3])); hq.y = *(uint32_t*)&h;
    h = __halves2half2(__int2half_rn(qv[4]), __int2half_rn(qv[5])); hq.z = *(uint32_t*)&h;
    h = __halves2half2(__int2half_rn(qv[6]), __int2half_rn(qv[7])); hq.w = *(uint32_t*)&h;
    *reinterpret_cast<uint4*>(g_qh + (size_t)token * K_DIM + tid * 8) = hq;
}

// ---------------------------------------------------------------------------
// PTX helpers (TMA + mbarrier)
// ---------------------------------------------------------------------------
__device__ __forceinline__ void mbar_init(uint32_t a, uint32_t cnt) {
    asm volatile("mbarrier.init.shared.b64 [%0], %1;" :: "r"(a), "r"(cnt) : "memory");
}
__device__ __forceinline__ void mbar_arrive(uint32_t a) {
    asm volatile("mbarrier.arrive.shared.b64 _, [%0];" :: "r"(a) : "memory");
}
__device__ __forceinline__ void mbar_expect_tx(uint32_t a, uint32_t bytes) {
    asm volatile("mbarrier.arrive.expect_tx.shared.b64 _, [%0], %1;" :: "r"(a), "r"(bytes) : "memory");
}
__device__ __forceinline__ void mbar_wait(uint32_t a, uint32_t parity) {
    asm volatile(
        "{\n\t.reg .pred P;\n"
        "W1_%=:\n\t"
        "mbarrier.try_wait.parity.acquire.cta.shared::cta.b64 P, [%0], %1, 0x989680;\n\t"
        "@P bra.uni W2_%=;\n\t"
        "bra.uni W1_%=;\n"
        "W2_%=:\n\t}"
        :: "r"(a), "r"(parity) : "memory");
}
__device__ __forceinline__ void tma3d(uint32_t smem, const CUtensorMap* map, int x, int y, uint32_t mbar) {
    asm volatile(
        "cp.async.bulk.tensor.3d.shared::cta.global.tile.mbarrier::complete_tx::bytes "
        "[%0], [%1, {%2, %3, %4}], [%5];"
        :: "r"(smem), "l"(map), "r"(x), "r"(y), "r"(0), "r"(mbar) : "memory");
}
__device__ __forceinline__ void ldsm4(uint32_t& r0, uint32_t& r1, uint32_t& r2, uint32_t& r3,
                                      uint32_t addr) {
    asm volatile("ldmatrix.sync.aligned.m8n8.x4.shared.b16 {%0,%1,%2,%3}, [%4];"
                 : "=r"(r0), "=r"(r1), "=r"(r2), "=r"(r3) : "r"(addr));
}

// ---------------------------------------------------------------------------
// Kernel 2: fp16 HMMA GEMM, TMA + full/empty mbarrier pipeline with the
// CORRECTED parity protocol:
//   - prologue fills ALL NSTAGE stages (chunks 0..2), no waits (fresh bars)
//   - producer refill of stage s for chunk kt+NSTAGE waits EMPTY(s) at
//     parity starting 0 (blocks until all 256 round-kt consumer arrivals)
//   - consumers arrive EMPTY after their MMAs (ldsm operands consumed by
//     HMMA issue => smem reads complete before any refill)
// No mainloop __syncthreads. 128x128 tile, 2 CTAs/SM, one 2048-CTA launch.
// ---------------------------------------------------------------------------
__global__ __launch_bounds__(256, 2) void gemm_f16_kernel(
    const __grid_constant__ CUtensorMap tma_a,
    const __grid_constant__ CUtensorMap tma_b,
    const float* __restrict__ w_scale,
    const float* __restrict__ bias,
    float* __restrict__ out)
{
    extern __shared__ char smem[];
    const uint32_t sb = (uint32_t)__cvta_generic_to_shared(smem);

    const int tid = threadIdx.x;
    const int lane = tid & 31;
    const int warp = tid >> 5;
    const int warpM = warp >> 2;   // 0..1 (64 rows)
    const int warpN = warp & 3;    // 0..3 (32 cols)
    const int g = lane >> 2;
    const int tg = lane & 3;

    const int m0 = blockIdx.y * BM;
    const int n0 = blockIdx.x * BN;

    if (tid == 0) {
        #pragma unroll
        for (int s = 0; s < NSTAGE; s++) {
            mbar_init(sb + FULL_BAR(s), 1);
            mbar_init(sb + EMPTY_BAR(s), 256);
        }
    }
    __syncthreads();

    // Prologue: fill ALL NSTAGE stages (chunks 0..NSTAGE-1). Fresh barriers,
    // no empty-wait needed (this is the round-0 "free pass", done explicitly).
    if (tid == 0) {
        #pragma unroll
        for (int s = 0; s < NSTAGE; s++) {
            mbar_expect_tx(sb + FULL_BAR(s), STAGE_B);
            tma3d(sb + s * STAGE_B,         &tma_a, s * 128, m0, sb + FULL_BAR(s));
            tma3d(sb + s * STAGE_B + 16384, &tma_b, s * 128, n0, sb + FULL_BAR(s));
        }
    }

    float acc[4][4][4];
    #pragma unroll
    for (int mi = 0; mi < 4; mi++)
        #pragma unroll
        for (int ni = 0; ni < 4; ni++)
            #pragma unroll
            for (int r = 0; r < 4; r++) acc[mi][ni][r] = 0.0f;

    // ldmatrix lane rows (validated layout) + SW128 per-lane XOR masks.
    const int aRow = warpM * 64 + (lane & 7) + ((lane >> 3) & 1) * 8;   // + mi*16
    const int aKof = (lane >> 4) * 16;
    const int bRow = warpN * 32 + (lane >> 4) * 8 + (lane & 7);         // + j2*16
    const int bKof = ((lane >> 3) & 1) * 16;
    const int aXor = (aRow & 7) * 16;
    const int bXor = (bRow & 7) * 16;

    int cstage = 0, cph = 0;   // consumer cursor (full bars)
    int pph = 0;               // producer empty-wait parity (starts 0: block
                               // until round-0 arrivals; stage == cstage)

    for (int kt = 0; kt < NKT; kt++) {
        // Wait for this stage's TMA data.
        mbar_wait(sb + FULL_BAR(cstage), cph);
        const uint32_t aBase = sb + cstage * STAGE_B;
        const uint32_t bBase = aBase + 16384;

        #pragma unroll
        for (int ks = 0; ks < 4; ks++) {
            const int k0 = ks * 32;
            uint32_t afr[4][4];
            #pragma unroll
            for (int mi = 0; mi < 4; mi++) {
                const int row = aRow + mi * 16;
                ldsm4(afr[mi][0], afr[mi][1], afr[mi][2], afr[mi][3],
                      aBase + row * 128 + ((k0 + aKof) ^ aXor));
            }
            uint32_t bfr[4][2];
            #pragma unroll
            for (int j2 = 0; j2 < 2; j2++) {
                const int row = bRow + j2 * 16;
                uint32_t b0, b1, b2, b3;
                ldsm4(b0, b1, b2, b3, bBase + row * 128 + ((k0 + bKof) ^ bXor));
                bfr[2 * j2][0] = b0; bfr[2 * j2][1] = b1;
                bfr[2 * j2 + 1][0] = b2; bfr[2 * j2 + 1][1] = b3;
            }
            #pragma unroll
            for (int mi = 0; mi < 4; mi++)
                #pragma unroll
                for (int ni = 0; ni < 4; ni++) {
                    asm volatile(
                        "mma.sync.aligned.m16n8k16.row.col.f32.f16.f16.f32 "
                        "{%0,%1,%2,%3}, {%4,%5,%6,%7}, {%8,%9}, {%0,%1,%2,%3};\n"
                        : "+f"(acc[mi][ni][0]), "+f"(acc[mi][ni][1]),
                          "+f"(acc[mi][ni][2]), "+f"(acc[mi][ni][3])
                        : "r"(afr[mi][0]), "r"(afr[mi][1]), "r"(afr[mi][2]), "r"(afr[mi][3]),
                          "r"(bfr[ni][0]), "r"(bfr[ni][1]));
                }
        }

        // Signal this stage consumed. HMMA issue consumed all ldsm results,
        // so smem reads of this stage are complete before the arrive.
        mbar_arrive(sb + EMPTY_BAR(cstage));

        // Producer: refill the just-consumed stage with chunk kt+NSTAGE,
        // after ALL 256 arrivals of this round (parity pph, starts 0).
        const int pf = kt + NSTAGE;
        if (tid == 0 && pf < NKT) {
            mbar_wait(sb + EMPTY_BAR(cstage), pph);
            mbar_expect_tx(sb + FULL_BAR(cstage), STAGE_B);
            tma3d(sb + cstage * STAGE_B,         &tma_a, pf * 128, m0, sb + FULL_BAR(cstage));
            tma3d(sb + cstage * STAGE_B + 16384, &tma_b, pf * 128, n0, sb + FULL_BAR(cstage));
        }

        if (++cstage == NSTAGE) { cstage = 0; cph ^= 1; pph ^= 1; }
    }

    // Epilogue: dequant + bias, round through fp16, store fp32 (validated).
    #pragma unroll
    for (int mi = 0; mi < 4; mi++) {
        const int r0 = m0 + warpM * 64 + mi * 16 + g;
        const float s0 = g_scales[r0];
        const float s1 = g_scales[r0 + 8];
        #pragma unroll
        for (int ni = 0; ni < 4; ni++) {
            const int c = n0 + warpN * 32 + ni * 8 + tg * 2;
            const float w0 = w_scale[c], w1 = w_scale[c + 1];
            const float b0 = bias[c],    b1 = bias[c + 1];
            float2 o0, o1;
            o0.x = __half2float(__float2half_rn(acc[mi][ni][0] * s0 * w0 + b0));
            o0.y = __half2float(__float2half_rn(acc[mi][ni][1] * s0 * w1 + b1));
            o1.x = __half2float(__float2half_rn(acc[mi][ni][2] * s1 * w0 + b0));
            o1.y = __half2float(__float2half_rn(acc[mi][ni][3] * s1 * w1 + b1));
            *reinterpret_cast<float2*>(out + (size_t)r0 * N_DIM + c) = o0;
            *reinterpret_cast<float2*>(out + (size_t)(r0 + 8) * N_DIM + c) = o1;
        }
    }
}

// ---------------------------------------------------------------------------
// Host launcher
// ---------------------------------------------------------------------------
typedef CUresult (*PFN_encodeTiled)(
    CUtensorMap*, CUtensorMapDataType, cuuint32_t, void*,
    const cuuint64_t*, const cuuint64_t*, const cuuint32_t*, const cuuint32_t*,
    CUtensorMapInterleave, CUtensorMapSwizzle, CUtensorMapL2promotion,
    CUtensorMapFloatOOBfill);

extern "C" void kernel_launch(void* const* d_in, const int* in_sizes, int n_in,
                              void* d_out, int out_size) {
    const float* x       = (const float*)d_in[0];
    const int*   weight  = (const int*)d_in[1];   // int8 marshalled as int32
    const float* w_scale = (const float*)d_in[2];
    const float* bias    = (const float*)d_in[3];
    float* out = (float*)d_out;

    pack_w_kernel<<<(N_DIM * K_DIM / 4) / 256, 256>>>(weight);
    quant_kernel<<<M_TOKENS, 256>>>(x);

    void* qptr = nullptr;
    void* wptr = nullptr;
    cudaGetSymbolAddress(&qptr, g_qh);
    cudaGetSymbolAddress(&wptr, g_wh);

    PFN_encodeTiled enc = nullptr;
    cudaDriverEntryPointQueryResult qres;
    cudaGetDriverEntryPointByVersion("cuTensorMapEncodeTiled", (void**)&enc, 12000,
                                     cudaEnableDefault, &qres);

    // Byte-typed views of the fp16 matrices: dims {K bytes, rows, 1}, SW128.
    CUtensorMap ta, tb;
    cuuint64_t dimsA[3] = {K_DIM * 2, M_TOKENS, 1};
    cuuint64_t strA[2]  = {K_DIM * 2, (cuuint64_t)(K_DIM * 2) * M_TOKENS};
    cuuint64_t dimsB[3] = {K_DIM * 2, N_DIM, 1};
    cuuint64_t strB[2]  = {K_DIM * 2, (cuuint64_t)(K_DIM * 2) * N_DIM};
    cuuint32_t box[3]   = {128, 128, 1};
    cuuint32_t es[3]    = {1, 1, 1};

    enc(&ta, CU_TENSOR_MAP_DATA_TYPE_UINT8, 3, qptr, dimsA, strA, box, es,
        CU_TENSOR_MAP_INTERLEAVE_NONE, CU_TENSOR_MAP_SWIZZLE_128B,
        CU_TENSOR_MAP_L2_PROMOTION_L2_128B, CU_TENSOR_MAP_FLOAT_OOB_FILL_NONE);
    enc(&tb, CU_TENSOR_MAP_DATA_TYPE_UINT8, 3, wptr, dimsB, strB, box, es,
        CU_TENSOR_MAP_INTERLEAVE_NONE, CU_TENSOR_MAP_SWIZZLE_128B,
        CU_TENSOR_MAP_L2_PROMOTION_L2_128B, CU_TENSOR_MAP_FLOAT_OOB_FILL_NONE);

    cudaFuncSetAttribute(gemm_f16_kernel, cudaFuncAttributeMaxDynamicSharedMemorySize, SMEM_TOTAL);
    dim3 grid(N_DIM / BN, M_TOKENS / BM);   // (16, 128) = 2048 CTAs, one launch
    gemm_f16_kernel<<<grid, 256, SMEM_TOTAL>>>(ta, tb, w_scale, bias, out);
}

// round 16
// speedup vs baseline: 1.8181x; 1.0065x over previous
#include <cuda_runtime.h>
#include <cuda.h>
#include <cuda_fp16.h>
#include <cstdint>

// Problem shape (fixed by dataset)
#define M_TOKENS 16384
#define K_DIM    2048
#define N_DIM    2048
#define EPS      1e-7f

// GEMM tiling: 128x128 CTA tile, K-chunk = 64 fp16 = 128 B per stage
#define BM 128
#define BN 128
#define NSTAGE 3
#define NKT 32
#define STAGE_B 32768                 // A 16KB + B 16KB, SW128-swizzled, pitch 128
#define SMEM_BARS (NSTAGE * STAGE_B)  // 98304
#define FULL_BAR(s)  (SMEM_BARS + (s) * 8)
#define EMPTY_BAR(s) (SMEM_BARS + 32 + (s) * 8)
#define SMEM_TOTAL (SMEM_BARS + 64)

// Prep-kernel grid split
#define PACK_BLOCKS 4096              // N*K/4/256
#define QUANT_BLOCKS M_TOKENS

// Scratch (device globals)
__device__ __align__(1024) __half g_qh[(size_t)M_TOKENS * K_DIM];  // fp16 activations
__device__ __align__(1024) __half g_wh[(size_t)N_DIM * K_DIM];     // fp16 weights
__device__ float g_scales[M_TOKENS];

// ---------------------------------------------------------------------------
// Kernel 0+1 merged: weight pack (blocks [0, PACK_BLOCKS)) and per-token
// quantization (blocks [PACK_BLOCKS, PACK_BLOCKS+QUANT_BLOCKS)).
// Both memory-bound; merging overlaps them and drops a launch boundary.
// ---------------------------------------------------------------------------
__global__ __launch_bounds__(256) void prep_kernel(const float* __restrict__ x,
                                                   const int* __restrict__ w32) {
    if (blockIdx.x < PACK_BLOCKS) {
        const int idx = blockIdx.x * blockDim.x + threadIdx.x;
        int4 v = reinterpret_cast<const int4*>(w32)[idx];
        __half2 h0 = __halves2half2(__int2half_rn(v.x), __int2half_rn(v.y));
        __half2 h1 = __halves2half2(__int2half_rn(v.z), __int2half_rn(v.w));
        uint2 hp = make_uint2(*(uint32_t*)&h0, *(uint32_t*)&h1);
        reinterpret_cast<uint2*>(g_wh)[idx] = hp;
        return;
    }

    const int token = blockIdx.x - PACK_BLOCKS;
    const int tid = threadIdx.x;
    const int lane = tid & 31;
    const int warp = tid >> 5;

    const float4* xr = reinterpret_cast<const float4*>(x + (size_t)token * K_DIM);
    float4 v0 = xr[tid * 2 + 0];
    float4 v1 = xr[tid * 2 + 1];

    float m = fabsf(v0.x);
    m = fmaxf(m, fabsf(v0.y)); m = fmaxf(m, fabsf(v0.z)); m = fmaxf(m, fabsf(v0.w));
    m = fmaxf(m, fabsf(v1.x)); m = fmaxf(m, fabsf(v1.y));
    m = fmaxf(m, fabsf(v1.z)); m = fmaxf(m, fabsf(v1.w));

    #pragma unroll
    for (int off = 16; off > 0; off >>= 1)
        m = fmaxf(m, __shfl_xor_sync(0xFFFFFFFFu, m, off));

    __shared__ float wmax[8];
    if (lane == 0) wmax[warp] = m;
    __syncthreads();
    if (warp == 0) {
        float t = (lane < 8) ? wmax[lane] : 0.0f;
        #pragma unroll
        for (int off = 4; off > 0; off >>= 1)
            t = fmaxf(t, __shfl_xor_sync(0xFFFFFFFFu, t, off));
        if (lane == 0) wmax[0] = t;
    }
    __syncthreads();
    const float absmax = wmax[0];
    const float scale = fmaxf(absmax, EPS) / 127.0f;

    if (tid == 0) g_scales[token] = scale;

    const float inv = 1.0f / scale;
    float vals[8] = {v0.x, v0.y, v0.z, v0.w, v1.x, v1.y, v1.z, v1.w};
    int qv[8];
    #pragma unroll
    for (int i = 0; i < 8; i++) {
        float q = rintf(vals[i] * inv);
        q = fminf(fmaxf(q, -128.0f), 127.0f);
        qv[i] = (int)q;
    }
    uint4 hq;
    __half2 h;
    h = __halves2half2(__int2half_rn(qv[0]), __int2half_rn(qv[1])); hq.x = *(uint32_t*)&h;
    h = __halves2half2(__int2half_rn(qv[2]), __int2half_rn(qv[3])); hq.y = *(uint32_t*)&h;
    h = __halves2half2(__int2half_rn(qv[4]), __int2half_rn(qv[5])); hq.z = *(uint32_t*)&h;
    h = __halves2half2(__int2half_rn(qv[6]), __int2half_rn(qv[7])); hq.w = *(uint32_t*)&h;
    *reinterpret_cast<uint4*>(g_qh + (size_t)token * K_DIM + tid * 8) = hq;
}

// ---------------------------------------------------------------------------
// PTX helpers (TMA + mbarrier)
// ---------------------------------------------------------------------------
__device__ __forceinline__ void mbar_init(uint32_t a, uint32_t cnt) {
    asm volatile("mbarrier.init.shared.b64 [%0], %1;" :: "r"(a), "r"(cnt) : "memory");
}
__device__ __forceinline__ void mbar_arrive(uint32_t a) {
    asm volatile("mbarrier.arrive.shared.b64 _, [%0];" :: "r"(a) : "memory");
}
__device__ __forceinline__ void mbar_expect_tx(uint32_t a, uint32_t bytes) {
    asm volatile("mbarrier.arrive.expect_tx.shared.b64 _, [%0], %1;" :: "r"(a), "r"(bytes) : "memory");
}
__device__ __forceinline__ void mbar_wait(uint32_t a, uint32_t parity) {
    asm volatile(
        "{\n\t.reg .pred P;\n"
        "W1_%=:\n\t"
        "mbarrier.try_wait.parity.acquire.cta.shared::cta.b64 P, [%0], %1, 0x989680;\n\t"
        "@P bra.uni W2_%=;\n\t"
        "bra.uni W1_%=;\n"
        "W2_%=:\n\t}"
        :: "r"(a), "r"(parity) : "memory");
}
__device__ __forceinline__ void tma3d(uint32_t smem, const CUtensorMap* map, int x, int y, uint32_t mbar) {
    asm volatile(
        "cp.async.bulk.tensor.3d.shared::cta.global.tile.mbarrier::complete_tx::bytes "
        "[%0], [%1, {%2, %3, %4}], [%5];"
        :: "r"(smem), "l"(map), "r"(x), "r"(y), "r"(0), "r"(mbar) : "memory");
}
__device__ __forceinline__ void ldsm4(uint32_t& r0, uint32_t& r1, uint32_t& r2, uint32_t& r3,
                                      uint32_t addr) {
    asm volatile("ldmatrix.sync.aligned.m8n8.x4.shared.b16 {%0,%1,%2,%3}, [%4];"
                 : "=r"(r0), "=r"(r1), "=r"(r2), "=r"(r3) : "r"(addr));
}

// ---------------------------------------------------------------------------
// Kernel 2: fp16 HMMA GEMM, TMA + full/empty mbarrier pipeline (validated
// R14 protocol) with warp-elected EMPTY arrivals (count 8, lane 0 only —
// mma.sync convergence guarantees all lanes' smem reads precede the arrive).
// 128x128 tile, 2 CTAs/SM, one 2048-CTA launch.
// ---------------------------------------------------------------------------
__global__ __launch_bounds__(256, 2) void gemm_f16_kernel(
    const __grid_constant__ CUtensorMap tma_a,
    const __grid_constant__ CUtensorMap tma_b,
    const float* __restrict__ w_scale,
    const float* __restrict__ bias,
    float* __restrict__ out)
{
    extern __shared__ char smem[];
    const uint32_t sb = (uint32_t)__cvta_generic_to_shared(smem);

    const int tid = threadIdx.x;
    const int lane = tid & 31;
    const int warp = tid >> 5;
    const int warpM = warp >> 2;   // 0..1 (64 rows)
    const int warpN = warp & 3;    // 0..3 (32 cols)
    const int g = lane >> 2;
    const int tg = lane & 3;

    const int m0 = blockIdx.y * BM;
    const int n0 = blockIdx.x * BN;

    if (tid == 0) {
        #pragma unroll
        for (int s = 0; s < NSTAGE; s++) {
            mbar_init(sb + FULL_BAR(s), 1);
            mbar_init(sb + EMPTY_BAR(s), 8);   // one arrive per warp
        }
    }
    __syncthreads();

    // Prologue: fill ALL NSTAGE stages (chunks 0..NSTAGE-1) on fresh barriers.
    if (tid == 0) {
        #pragma unroll
        for (int s = 0; s < NSTAGE; s++) {
            mbar_expect_tx(sb + FULL_BAR(s), STAGE_B);
            tma3d(sb + s * STAGE_B,         &tma_a, s * 128, m0, sb + FULL_BAR(s));
            tma3d(sb + s * STAGE_B + 16384, &tma_b, s * 128, n0, sb + FULL_BAR(s));
        }
    }

    float acc[4][4][4];
    #pragma unroll
    for (int mi = 0; mi < 4; mi++)
        #pragma unroll
        for (int ni = 0; ni < 4; ni++)
            #pragma unroll
            for (int r = 0; r < 4; r++) acc[mi][ni][r] = 0.0f;

    // ldmatrix lane rows (validated layout) + SW128 per-lane XOR masks.
    const int aRow = warpM * 64 + (lane & 7) + ((lane >> 3) & 1) * 8;   // + mi*16
    const int aKof = (lane >> 4) * 16;
    const int bRow = warpN * 32 + (lane >> 4) * 8 + (lane & 7);         // + j2*16
    const int bKof = ((lane >> 3) & 1) * 16;
    const int aXor = (aRow & 7) * 16;
    const int bXor = (bRow & 7) * 16;

    int cstage = 0, cph = 0;   // consumer cursor (full bars)
    int pph = 0;               // producer empty-wait parity (starts 0)

    for (int kt = 0; kt < NKT; kt++) {
        // Wait for this stage's TMA data.
        mbar_wait(sb + FULL_BAR(cstage), cph);
        const uint32_t aBase = sb + cstage * STAGE_B;
        const uint32_t bBase = aBase + 16384;

        #pragma unroll
        for (int ks = 0; ks < 4; ks++) {
            const int k0 = ks * 32;
            uint32_t afr[4][4];
            #pragma unroll
            for (int mi = 0; mi < 4; mi++) {
                const int row = aRow + mi * 16;
                ldsm4(afr[mi][0], afr[mi][1], afr[mi][2], afr[mi][3],
                      aBase + row * 128 + ((k0 + aKof) ^ aXor));
            }
            uint32_t bfr[4][2];
            #pragma unroll
            for (int j2 = 0; j2 < 2; j2++) {
                const int row = bRow + j2 * 16;
                uint32_t b0, b1, b2, b3;
                ldsm4(b0, b1, b2, b3, bBase + row * 128 + ((k0 + bKof) ^ bXor));
                bfr[2 * j2][0] = b0; bfr[2 * j2][1] = b1;
                bfr[2 * j2 + 1][0] = b2; bfr[2 * j2 + 1][1] = b3;
            }
            #pragma unroll
            for (int mi = 0; mi < 4; mi++)
                #pragma unroll
                for (int ni = 0; ni < 4; ni++) {
                    asm volatile(
                        "mma.sync.aligned.m16n8k16.row.col.f32.f16.f16.f32 "
                        "{%0,%1,%2,%3}, {%4,%5,%6,%7}, {%8,%9}, {%0,%1,%2,%3};\n"
                        : "+f"(acc[mi][ni][0]), "+f"(acc[mi][ni][1]),
                          "+f"(acc[mi][ni][2]), "+f"(acc[mi][ni][3])
                        : "r"(afr[mi][0]), "r"(afr[mi][1]), "r"(afr[mi][2]), "r"(afr[mi][3]),
                          "r"(bfr[ni][0]), "r"(bfr[ni][1]));
                }
        }

        // Warp-elected empty arrive: mma.sync converged all lanes, so lane 0's
        // arrive is ordered after every lane's smem reads of this stage.
        if (lane == 0) mbar_arrive(sb + EMPTY_BAR(cstage));

        // Producer: refill the just-consumed stage with chunk kt+NSTAGE,
        // after all 8 warp arrivals of this round (parity pph).
        const int pf = kt + NSTAGE;
        if (tid == 0 && pf < NKT) {
            mbar_wait(sb + EMPTY_BAR(cstage), pph);
            mbar_expect_tx(sb + FULL_BAR(cstage), STAGE_B);
            tma3d(sb + cstage * STAGE_B,         &tma_a, pf * 128, m0, sb + FULL_BAR(cstage));
            tma3d(sb + cstage * STAGE_B + 16384, &tma_b, pf * 128, n0, sb + FULL_BAR(cstage));
        }

        if (++cstage == NSTAGE) { cstage = 0; cph ^= 1; pph ^= 1; }
    }

    // Epilogue: dequant + bias, round through fp16, store fp32 (validated).
    #pragma unroll
    for (int mi = 0; mi < 4; mi++) {
        const int r0 = m0 + warpM * 64 + mi * 16 + g;
        const float s0 = g_scales[r0];
        const float s1 = g_scales[r0 + 8];
        #pragma unroll
        for (int ni = 0; ni < 4; ni++) {
            const int c = n0 + warpN * 32 + ni * 8 + tg * 2;
            const float w0 = w_scale[c], w1 = w_scale[c + 1];
            const float b0 = bias[c],    b1 = bias[c + 1];
            float2 o0, o1;
            o0.x = __half2float(__float2half_rn(acc[mi][ni][0] * s0 * w0 + b0));
            o0.y = __half2float(__float2half_rn(acc[mi][ni][1] * s0 * w1 + b1));
            o1.x = __half2float(__float2half_rn(acc[mi][ni][2] * s1 * w0 + b0));
            o1.y = __half2float(__float2half_rn(acc[mi][ni][3] * s1 * w1 + b1));
            *reinterpret_cast<float2*>(out + (size_t)r0 * N_DIM + c) = o0;
            *reinterpret_cast<float2*>(out + (size_t)(r0 + 8) * N_DIM + c) = o1;
        }
    }
}

// ---------------------------------------------------------------------------
// Host launcher
// ---------------------------------------------------------------------------
typedef CUresult (*PFN_encodeTiled)(
    CUtensorMap*, CUtensorMapDataType, cuuint32_t, void*,
    const cuuint64_t*, const cuuint64_t*, const cuuint32_t*, const cuuint32_t*,
    CUtensorMapInterleave, CUtensorMapSwizzle, CUtensorMapL2promotion,
    CUtensorMapFloatOOBfill);

extern "C" void kernel_launch(void* const* d_in, const int* in_sizes, int n_in,
                              void* d_out, int out_size) {
    const float* x       = (const float*)d_in[0];
    const int*   weight  = (const int*)d_in[1];   // int8 marshalled as int32
    const float* w_scale = (const float*)d_in[2];
    const float* bias    = (const float*)d_in[3];
    float* out = (float*)d_out;

    prep_kernel<<<PACK_BLOCKS + QUANT_BLOCKS, 256>>>(x, weight);

    void* qptr = nullptr;
    void* wptr = nullptr;
    cudaGetSymbolAddress(&qptr, g_qh);
    cudaGetSymbolAddress(&wptr, g_wh);

    PFN_encodeTiled enc = nullptr;
    cudaDriverEntryPointQueryResult qres;
    cudaGetDriverEntryPointByVersion("cuTensorMapEncodeTiled", (void**)&enc, 12000,
                                     cudaEnableDefault, &qres);

    // Byte-typed views of the fp16 matrices: dims {K bytes, rows, 1}, SW128.
    CUtensorMap ta, tb;
    cuuint64_t dimsA[3] = {K_DIM * 2, M_TOKENS, 1};
    cuuint64_t strA[2]  = {K_DIM * 2, (cuuint64_t)(K_DIM * 2) * M_TOKENS};
    cuuint64_t dimsB[3] = {K_DIM * 2, N_DIM, 1};
    cuuint64_t strB[2]  = {K_DIM * 2, (cuuint64_t)(K_DIM * 2) * N_DIM};
    cuuint32_t box[3]   = {128, 128, 1};
    cuuint32_t es[3]    = {1, 1, 1};

    enc(&ta, CU_TENSOR_MAP_DATA_TYPE_UINT8, 3, qptr, dimsA, strA, box, es,
        CU_TENSOR_MAP_INTERLEAVE_NONE, CU_TENSOR_MAP_SWIZZLE_128B,
        CU_TENSOR_MAP_L2_PROMOTION_L2_128B, CU_TENSOR_MAP_FLOAT_OOB_FILL_NONE);
    enc(&tb, CU_TENSOR_MAP_DATA_TYPE_UINT8, 3, wptr, dimsB, strB, box, es,
        CU_TENSOR_MAP_INTERLEAVE_NONE, CU_TENSOR_MAP_SWIZZLE_128B,
        CU_TENSOR_MAP_L2_PROMOTION_L2_128B, CU_TENSOR_MAP_FLOAT_OOB_FILL_NONE);

    cudaFuncSetAttribute(gemm_f16_kernel, cudaFuncAttributeMaxDynamicSharedMemorySize, SMEM_TOTAL);
    dim3 grid(N_DIM / BN, M_TOKENS / BM);   // (16, 128) = 2048 CTAs, one launch
    gemm_f16_kernel<<<grid, 256, SMEM_TOTAL>>>(ta, tb, w_scale, bias, out);
}